// round 9
// baseline (speedup 1.0000x reference)
#include <cuda_runtime.h>
#include <cuda_bf16.h>

#define NN 512
#define EE (NN * NN)
#define NB 256           // histogram blocks
#define CHUNK (EE / NB)  // 1024 edges per block

// ---------------- scratch ----------------
__device__ int   g_is64;
__device__ int   g_nonzero;
__device__ int   g_start[NN + 1];
__device__ float g_invcnt[NN];
__device__ int   g_tot[NN];
__device__ int   g_bh[NB * NN];      // [block][bin] counts (coalesced layout)
__device__ int   g_bhoff[NB * NN];   // [block][bin] start offsets
__device__ int   g_src_sorted[EE];
__device__ __align__(16) float g_ea_sorted[EE * 8];
__device__ __align__(16) float g_h1[NN * 36];
__device__ __align__(16) float g_h2[NN * 24];
__device__ __align__(16) float g_h3[NN * 5];

// ---------------- packed f32x2 helpers ----------------
__device__ __forceinline__ unsigned long long pk2(float lo, float hi) {
    unsigned long long r;
    asm("mov.b64 %0,{%1,%2};" : "=l"(r) : "f"(lo), "f"(hi));
    return r;
}
__device__ __forceinline__ void upk2(unsigned long long v, float& lo, float& hi) {
    asm("mov.b64 {%0,%1},%2;" : "=f"(lo), "=f"(hi) : "l"(v));
}
__device__ __forceinline__ unsigned long long ffma2(unsigned long long a,
                                                    unsigned long long b,
                                                    unsigned long long c) {
    unsigned long long d;
    asm("fma.rn.f32x2 %0,%1,%2,%3;" : "=l"(d) : "l"(a), "l"(b), "l"(c));
    return d;
}

__device__ __forceinline__ int load_src(const int* raw, int e, int is64) {
    return (is64 ? raw[2 * e] : raw[e]) & (NN - 1);
}
__device__ __forceinline__ int load_dst(const int* raw, int e, int is64) {
    return (is64 ? raw[2 * EE + 2 * e] : raw[EE + e]) & (NN - 1);
}

// ---------------- dtype detect ----------------
__global__ void detect_kernel(const int* __restrict__ raw) {
    int t = threadIdx.x;
    if (t == 0) g_nonzero = 0;
    __syncthreads();
    int idx = 2 * (t * (EE / 512)) + 1;
    if (t < 256 && raw[idx] != 0) atomicOr(&g_nonzero, 1);
    __syncthreads();
    if (t == 0) g_is64 = (g_nonzero == 0) ? 1 : 0;
}

// ---------------- phase A: per-block histogram (smem), coalesced writes ------
__global__ void __launch_bounds__(256) histA_kernel(const int* __restrict__ raw) {
    __shared__ int h[NN];
    int tid = threadIdx.x;
    int is64 = g_is64;
    for (int i = tid; i < NN; i += 256) h[i] = 0;
    __syncthreads();
    int base = blockIdx.x * CHUNK;
#pragma unroll
    for (int k = 0; k < CHUNK / 256; k++) {
        int e = base + k * 256 + tid;
        atomicAdd(&h[load_dst(raw, e, is64)], 1);
    }
    __syncthreads();
    for (int i = tid; i < NN; i += 256)
        g_bh[blockIdx.x * NN + i] = h[i];
}

// ---------------- phase B1: per-bin totals (coalesced column sums) ------------
__global__ void __launch_bounds__(64) totals_kernel() {
    int bin = blockIdx.x * 64 + threadIdx.x;
    int total = 0;
#pragma unroll 16
    for (int blk = 0; blk < NB; blk++) total += g_bh[blk * NN + bin];
    g_tot[bin] = total;
}

// ---------------- phase B2: scan of 512 bin totals ----------------------------
__global__ void __launch_bounds__(NN) scanB_kernel() {
    __shared__ int sc[NN];
    int t = threadIdx.x;
    int c = g_tot[t];
    sc[t] = c;
    __syncthreads();
    for (int off = 1; off < NN; off <<= 1) {
        int v = (t >= off) ? sc[t - off] : 0;
        __syncthreads();
        sc[t] += v;
        __syncthreads();
    }
    g_start[t] = sc[t] - c;
    if (t == NN - 1) g_start[NN] = sc[t];
    g_invcnt[t] = 1.0f / (float)(c > 1 ? c : 1);
}

// ---------------- phase B3: per-(block,bin) running offsets (coalesced) -------
__global__ void __launch_bounds__(64) offsets_kernel() {
    int bin = blockIdx.x * 64 + threadIdx.x;
    int run = g_start[bin];
#pragma unroll 8
    for (int blk = 0; blk < NB; blk++) {
        g_bhoff[blk * NN + bin] = run;
        run += g_bh[blk * NN + bin];
    }
}

// ---------------- phase C: rank via smem atomics, direct sorted writes --------
__global__ void __launch_bounds__(256) scatterC_kernel(const int* __restrict__ raw,
                                                       const float* __restrict__ ea) {
    __shared__ int loc[NN];
    int tid = threadIdx.x;
    int is64 = g_is64;
    for (int i = tid; i < NN; i += 256)
        loc[i] = g_bhoff[blockIdx.x * NN + i];
    __syncthreads();
    int base = blockIdx.x * CHUNK;
#pragma unroll
    for (int k = 0; k < CHUNK / 256; k++) {
        int e = base + k * 256 + tid;
        int d = load_dst(raw, e, is64);
        int s = load_src(raw, e, is64);
        int pos = atomicAdd(&loc[d], 1);
        const float* q = ea + (size_t)e * 6;
        float v0 = q[0], v1 = q[1], v2 = q[2], v3 = q[3], v4 = q[4], v5 = q[5];
        g_src_sorted[pos] = s;
        float4* w = (float4*)(g_ea_sorted + (size_t)pos * 8);
        w[0] = make_float4(v0, v1, v2, v3);
        w[1] = make_float4(v4, v5, 0.0f, 0.0f);
    }
}

// ---------------- per-tile compute helpers ----------------
template <int NP, int NE>
__device__ __forceinline__ void edge_tileN(const ulonglong2* tp,
                                           const unsigned long long ea2[][6],
                                           const float* xi, float* acc) {
#pragma unroll
    for (int p = 0; p < NP; p++) {
        ulonglong2 w01 = tp[4 * p + 0];
        ulonglong2 w23 = tp[4 * p + 1];
        ulonglong2 w45 = tp[4 * p + 2];
        ulonglong2 bb  = tp[4 * p + 3];
        unsigned long long t[NE];
#pragma unroll
        for (int j = 0; j < NE; j++) t[j] = bb.x;
#pragma unroll
        for (int j = 0; j < NE; j++) t[j] = ffma2(ea2[j][0], w01.x, t[j]);
#pragma unroll
        for (int j = 0; j < NE; j++) t[j] = ffma2(ea2[j][1], w01.y, t[j]);
#pragma unroll
        for (int j = 0; j < NE; j++) t[j] = ffma2(ea2[j][2], w23.x, t[j]);
#pragma unroll
        for (int j = 0; j < NE; j++) t[j] = ffma2(ea2[j][3], w23.y, t[j]);
#pragma unroll
        for (int j = 0; j < NE; j++) t[j] = ffma2(ea2[j][4], w45.x, t[j]);
#pragma unroll
        for (int j = 0; j < NE; j++) t[j] = ffma2(ea2[j][5], w45.y, t[j]);
        float a0 = acc[2 * p], a1 = acc[2 * p + 1];
#pragma unroll
        for (int j = 0; j < NE; j++) {
            float t0, t1; upk2(t[j], t0, t1);
            a0 = fmaf(xi[j], fmaxf(t0, 0.0f), a0);
            a1 = fmaf(xi[j], fmaxf(t1, 0.0f), a1);
        }
        acc[2 * p] = a0; acc[2 * p + 1] = a1;
    }
}

__device__ __forceinline__ void load_ea(int e, unsigned long long* ea2) {
    float4 eaA = *(const float4*)(g_ea_sorted + (size_t)e * 8);
    float4 eaB = *(const float4*)(g_ea_sorted + (size_t)e * 8 + 4);
    ea2[0] = pk2(eaA.x, eaA.x); ea2[1] = pk2(eaA.y, eaA.y);
    ea2[2] = pk2(eaA.z, eaA.z); ea2[3] = pk2(eaA.w, eaA.w);
    ea2[4] = pk2(eaB.x, eaB.x); ea2[5] = pk2(eaB.y, eaB.y);
}

// process NE edges starting at e with stride BLOCK
template <int IN, int NP, int NE, int BLOCK>
__device__ __forceinline__ void process_edges(const float* __restrict__ h_in,
                                              const float* sW, int e, float* acc) {
    int s[NE];
    unsigned long long ea2[NE][6];
#pragma unroll
    for (int j = 0; j < NE; j++) s[j] = g_src_sorted[e + j * BLOCK];
#pragma unroll
    for (int j = 0; j < NE; j++) load_ea(e + j * BLOCK, ea2[j]);

    if constexpr (IN == 1) {
        float xi[NE];
#pragma unroll
        for (int j = 0; j < NE; j++) xi[j] = h_in[s[j]];
        edge_tileN<NP, NE>((const ulonglong2*)sW, ea2, xi, acc);
    } else {
#pragma unroll 1
        for (int i4 = 0; i4 < IN / 4; i4++) {
            float4 xv[NE];
#pragma unroll
            for (int j = 0; j < NE; j++)
                xv[j] = *(const float4*)(h_in + (size_t)s[j] * IN + 4 * i4);
#pragma unroll
            for (int su = 0; su < 4; su++) {
                float xi[NE];
#pragma unroll
                for (int j = 0; j < NE; j++)
                    xi[j] = (su == 0) ? xv[j].x : (su == 1) ? xv[j].y
                          : (su == 2) ? xv[j].z : xv[j].w;
                const ulonglong2* tp =
                    (const ulonglong2*)(sW + (size_t)(i4 * 4 + su) * NP * 16);
                edge_tileN<NP, NE>(tp, ea2, xi, acc);
            }
        }
    }
}

// ---------------- fused NNConv layer (gather form) ----------------
template <int IN, int OUT, int OPAD, int BLOCK>
__global__ void __launch_bounds__(BLOCK) nnconv_kernel(
    const float* __restrict__ h_in,
    const float* __restrict__ W, const float* __restrict__ b,
    const float* __restrict__ root, const float* __restrict__ bias,
    float* __restrict__ h_out) {
    constexpr int NP = OPAD / 2;
    __shared__ __align__(16) float sW[IN * NP * 16];
    __shared__ float red[BLOCK / 32][OPAD];
    const int tid = threadIdx.x;

    for (int idx = tid; idx < IN * NP; idx += BLOCK) {
        int i = idx / NP, p = idx % NP;
        float* t = sW + idx * 16;
        int o0 = 2 * p, o1 = 2 * p + 1;
#pragma unroll
        for (int v = 0; v < 6; v++) {
            t[2 * v]     = (o0 < OUT) ? W[v * (IN * OUT) + i * OUT + o0] : 0.0f;
            t[2 * v + 1] = (o1 < OUT) ? W[v * (IN * OUT) + i * OUT + o1] : 0.0f;
        }
        t[12] = (o0 < OUT) ? b[i * OUT + o0] : 0.0f;
        t[13] = (o1 < OUT) ? b[i * OUT + o1] : 0.0f;
        t[14] = 0.0f; t[15] = 0.0f;
    }
    __syncthreads();

    const int n = blockIdx.x;
    const int e0 = g_start[n], e1 = g_start[n + 1];

    float acc[OPAD];
#pragma unroll
    for (int o = 0; o < OPAD; o++) acc[o] = 0.0f;

    int e = e0 + tid;
    for (; e + 3 * BLOCK < e1; e += 4 * BLOCK)
        process_edges<IN, NP, 4, BLOCK>(h_in, sW, e, acc);
    for (; e + BLOCK < e1; e += 2 * BLOCK)
        process_edges<IN, NP, 2, BLOCK>(h_in, sW, e, acc);
    for (; e < e1; e += BLOCK)
        process_edges<IN, NP, 1, BLOCK>(h_in, sW, e, acc);

    // warp reduce
#pragma unroll
    for (int o = 0; o < OPAD; o++) {
        float v = acc[o];
        v += __shfl_down_sync(0xffffffffu, v, 16);
        v += __shfl_down_sync(0xffffffffu, v, 8);
        v += __shfl_down_sync(0xffffffffu, v, 4);
        v += __shfl_down_sync(0xffffffffu, v, 2);
        v += __shfl_down_sync(0xffffffffu, v, 1);
        acc[o] = v;
    }
    if ((tid & 31) == 0) {
#pragma unroll
        for (int o = 0; o < OPAD; o++) red[tid >> 5][o] = acc[o];
    }
    __syncthreads();

    if (tid < OUT) {
        float s = 0.0f;
#pragma unroll
        for (int w = 0; w < BLOCK / 32; w++) s += red[w][tid];
        s *= g_invcnt[n];
        float r = 0.0f;
#pragma unroll
        for (int i = 0; i < IN; i++) r += h_in[(size_t)n * IN + i] * root[i * OUT + tid];
        float v = s + r + bias[tid];
        h_out[(size_t)n * OUT + tid] = fmaxf(v, 0.0f);
    }
}

// ---------------- CBT ----------------
__global__ void cbt_kernel(const float* __restrict__ h3, float* __restrict__ out) {
    __shared__ float sh[NN * 5];
    int tid = threadIdx.x;
    for (int i = tid; i < NN * 5; i += blockDim.x) sh[i] = h3[i];
    __syncthreads();
    int a = blockIdx.x;
    float ha[5];
#pragma unroll
    for (int f = 0; f < 5; f++) ha[f] = sh[a * 5 + f];
    float s = 0.0f;
#pragma unroll
    for (int f = 0; f < 5; f++) s += fabsf(sh[tid * 5 + f] - ha[f]);
    out[(size_t)a * NN + tid] = s;
}

// ---------------- launch ----------------
extern "C" void kernel_launch(void* const* d_in, const int* in_sizes, int n_in,
                              void* d_out, int out_size) {
    const float* x    = (const float*)d_in[0];
    const float* ea   = (const float*)d_in[1];
    const int*   eidx = (const int*)d_in[2];
    const float *W1 = (const float*)d_in[3],  *b1 = (const float*)d_in[4];
    const float *root1 = (const float*)d_in[5], *bias1 = (const float*)d_in[6];
    const float *W2 = (const float*)d_in[7],  *b2 = (const float*)d_in[8];
    const float *root2 = (const float*)d_in[9], *bias2 = (const float*)d_in[10];
    const float *W3 = (const float*)d_in[11], *b3 = (const float*)d_in[12];
    const float *root3 = (const float*)d_in[13], *bias3 = (const float*)d_in[14];
    float* out = (float*)d_out;

    detect_kernel<<<1, NN>>>(eidx);
    histA_kernel<<<NB, 256>>>(eidx);
    totals_kernel<<<NN / 64, 64>>>();
    scanB_kernel<<<1, NN>>>();
    offsets_kernel<<<NN / 64, 64>>>();
    scatterC_kernel<<<NB, 256>>>(eidx, ea);

    float* h1; cudaGetSymbolAddress((void**)&h1, g_h1);
    float* h2; cudaGetSymbolAddress((void**)&h2, g_h2);
    float* h3; cudaGetSymbolAddress((void**)&h3, g_h3);

    nnconv_kernel<1, 36, 36, 128><<<NN, 128>>>(x,  W1, b1, root1, bias1, h1);
    nnconv_kernel<36, 24, 24, 128><<<NN, 128>>>(h1, W2, b2, root2, bias2, h2);
    nnconv_kernel<24, 5, 6, 128><<<NN, 128>>>(h2, W3, b3, root3, bias3, h3);
    cbt_kernel<<<NN, NN>>>(h3, out);
}

// round 11
// speedup vs baseline: 1.0419x; 1.0419x over previous
#include <cuda_runtime.h>
#include <cuda_bf16.h>

#define NN 512
#define EE (NN * NN)
#define NB 256           // histogram blocks
#define CHUNK (EE / NB)  // 1024 edges per block
#define SPLIT 2
#define PSTRIDE 40       // padded per-part accumulator stride (>= max OPAD)

// ---------------- scratch ----------------
__device__ int   g_is64;
__device__ int   g_nonzero;
__device__ int   g_start[NN + 1];
__device__ float g_invcnt[NN];
__device__ int   g_tot[NN];
__device__ int   g_bh[NB * NN];      // [block][bin] counts (coalesced layout)
__device__ int   g_bhoff[NB * NN];   // [block][bin] start offsets
__device__ int   g_src_sorted[EE];
__device__ __align__(16) float g_ea_sorted[EE * 8];
__device__ __align__(16) float g_part[NN * SPLIT * PSTRIDE];
__device__ __align__(16) float g_h1[NN * 36];
__device__ __align__(16) float g_h2[NN * 24];
__device__ __align__(16) float g_h3[NN * 5];

// ---------------- packed f32x2 helpers ----------------
__device__ __forceinline__ unsigned long long pk2(float lo, float hi) {
    unsigned long long r;
    asm("mov.b64 %0,{%1,%2};" : "=l"(r) : "f"(lo), "f"(hi));
    return r;
}
__device__ __forceinline__ void upk2(unsigned long long v, float& lo, float& hi) {
    asm("mov.b64 {%0,%1},%2;" : "=f"(lo), "=f"(hi) : "l"(v));
}
__device__ __forceinline__ unsigned long long ffma2(unsigned long long a,
                                                    unsigned long long b,
                                                    unsigned long long c) {
    unsigned long long d;
    asm("fma.rn.f32x2 %0,%1,%2,%3;" : "=l"(d) : "l"(a), "l"(b), "l"(c));
    return d;
}

__device__ __forceinline__ int load_src(const int* raw, int e, int is64) {
    return (is64 ? raw[2 * e] : raw[e]) & (NN - 1);
}
__device__ __forceinline__ int load_dst(const int* raw, int e, int is64) {
    return (is64 ? raw[2 * EE + 2 * e] : raw[EE + e]) & (NN - 1);
}

// ---------------- dtype detect ----------------
__global__ void detect_kernel(const int* __restrict__ raw) {
    int t = threadIdx.x;
    if (t == 0) g_nonzero = 0;
    __syncthreads();
    int idx = 2 * (t * (EE / 512)) + 1;
    if (t < 256 && raw[idx] != 0) atomicOr(&g_nonzero, 1);
    __syncthreads();
    if (t == 0) g_is64 = (g_nonzero == 0) ? 1 : 0;
}

// ---------------- phase A: per-block histogram (smem), coalesced writes ------
__global__ void __launch_bounds__(256) histA_kernel(const int* __restrict__ raw) {
    __shared__ int h[NN];
    int tid = threadIdx.x;
    int is64 = g_is64;
    for (int i = tid; i < NN; i += 256) h[i] = 0;
    __syncthreads();
    int base = blockIdx.x * CHUNK;
#pragma unroll
    for (int k = 0; k < CHUNK / 256; k++) {
        int e = base + k * 256 + tid;
        atomicAdd(&h[load_dst(raw, e, is64)], 1);
    }
    __syncthreads();
    for (int i = tid; i < NN; i += 256)
        g_bh[blockIdx.x * NN + i] = h[i];
}

// ---------------- phase B1: per-bin totals (coalesced column sums) ------------
__global__ void __launch_bounds__(64) totals_kernel() {
    int bin = blockIdx.x * 64 + threadIdx.x;
    int total = 0;
#pragma unroll 16
    for (int blk = 0; blk < NB; blk++) total += g_bh[blk * NN + bin];
    g_tot[bin] = total;
}

// ---------------- phase B2: scan of 512 bin totals ----------------------------
__global__ void __launch_bounds__(NN) scanB_kernel() {
    __shared__ int sc[NN];
    int t = threadIdx.x;
    int c = g_tot[t];
    sc[t] = c;
    __syncthreads();
    for (int off = 1; off < NN; off <<= 1) {
        int v = (t >= off) ? sc[t - off] : 0;
        __syncthreads();
        sc[t] += v;
        __syncthreads();
    }
    g_start[t] = sc[t] - c;
    if (t == NN - 1) g_start[NN] = sc[t];
    g_invcnt[t] = 1.0f / (float)(c > 1 ? c : 1);
}

// ---------------- phase B3: per-(block,bin) running offsets (coalesced) -------
__global__ void __launch_bounds__(64) offsets_kernel() {
    int bin = blockIdx.x * 64 + threadIdx.x;
    int run = g_start[bin];
#pragma unroll 8
    for (int blk = 0; blk < NB; blk++) {
        g_bhoff[blk * NN + bin] = run;
        run += g_bh[blk * NN + bin];
    }
}

// ---------------- phase C: rank via smem atomics, direct sorted writes --------
__global__ void __launch_bounds__(256) scatterC_kernel(const int* __restrict__ raw,
                                                       const float* __restrict__ ea) {
    __shared__ int loc[NN];
    int tid = threadIdx.x;
    int is64 = g_is64;
    for (int i = tid; i < NN; i += 256)
        loc[i] = g_bhoff[blockIdx.x * NN + i];
    __syncthreads();
    int base = blockIdx.x * CHUNK;
#pragma unroll
    for (int k = 0; k < CHUNK / 256; k++) {
        int e = base + k * 256 + tid;
        int d = load_dst(raw, e, is64);
        int s = load_src(raw, e, is64);
        int pos = atomicAdd(&loc[d], 1);
        const float* q = ea + (size_t)e * 6;
        float v0 = q[0], v1 = q[1], v2 = q[2], v3 = q[3], v4 = q[4], v5 = q[5];
        g_src_sorted[pos] = s;
        float4* w = (float4*)(g_ea_sorted + (size_t)pos * 8);
        w[0] = make_float4(v0, v1, v2, v3);
        w[1] = make_float4(v4, v5, 0.0f, 0.0f);
    }
}

// ---------------- per-tile compute helpers (2-edge, proven best) --------------
template <int NP>
__device__ __forceinline__ void edge_tile(const ulonglong2* tp,
                                          const unsigned long long* ea2,
                                          float xi, float* acc) {
#pragma unroll
    for (int p = 0; p < NP; p++) {
        ulonglong2 w01 = tp[4 * p + 0];
        ulonglong2 w23 = tp[4 * p + 1];
        ulonglong2 w45 = tp[4 * p + 2];
        ulonglong2 bb  = tp[4 * p + 3];
        unsigned long long t = bb.x;
        t = ffma2(ea2[0], w01.x, t);
        t = ffma2(ea2[1], w01.y, t);
        t = ffma2(ea2[2], w23.x, t);
        t = ffma2(ea2[3], w23.y, t);
        t = ffma2(ea2[4], w45.x, t);
        t = ffma2(ea2[5], w45.y, t);
        float t0, t1; upk2(t, t0, t1);
        acc[2 * p]     = fmaf(xi, fmaxf(t0, 0.0f), acc[2 * p]);
        acc[2 * p + 1] = fmaf(xi, fmaxf(t1, 0.0f), acc[2 * p + 1]);
    }
}

template <int NP>
__device__ __forceinline__ void edge_tile2(const ulonglong2* tp,
                                           const unsigned long long* eaA,
                                           const unsigned long long* eaB,
                                           float xiA, float xiB, float* acc) {
#pragma unroll
    for (int p = 0; p < NP; p++) {
        ulonglong2 w01 = tp[4 * p + 0];
        ulonglong2 w23 = tp[4 * p + 1];
        ulonglong2 w45 = tp[4 * p + 2];
        ulonglong2 bb  = tp[4 * p + 3];
        unsigned long long tA = bb.x, tB = bb.x;
        tA = ffma2(eaA[0], w01.x, tA);  tB = ffma2(eaB[0], w01.x, tB);
        tA = ffma2(eaA[1], w01.y, tA);  tB = ffma2(eaB[1], w01.y, tB);
        tA = ffma2(eaA[2], w23.x, tA);  tB = ffma2(eaB[2], w23.x, tB);
        tA = ffma2(eaA[3], w23.y, tA);  tB = ffma2(eaB[3], w23.y, tB);
        tA = ffma2(eaA[4], w45.x, tA);  tB = ffma2(eaB[4], w45.x, tB);
        tA = ffma2(eaA[5], w45.y, tA);  tB = ffma2(eaB[5], w45.y, tB);
        float a0, a1, b0, b1;
        upk2(tA, a0, a1); upk2(tB, b0, b1);
        float s0 = fmaf(xiA, fmaxf(a0, 0.0f), acc[2 * p]);
        float s1 = fmaf(xiA, fmaxf(a1, 0.0f), acc[2 * p + 1]);
        acc[2 * p]     = fmaf(xiB, fmaxf(b0, 0.0f), s0);
        acc[2 * p + 1] = fmaf(xiB, fmaxf(b1, 0.0f), s1);
    }
}

__device__ __forceinline__ void load_ea(int e, unsigned long long* ea2) {
    float4 eaA = *(const float4*)(g_ea_sorted + (size_t)e * 8);
    float4 eaB = *(const float4*)(g_ea_sorted + (size_t)e * 8 + 4);
    ea2[0] = pk2(eaA.x, eaA.x); ea2[1] = pk2(eaA.y, eaA.y);
    ea2[2] = pk2(eaA.z, eaA.z); ea2[3] = pk2(eaA.w, eaA.w);
    ea2[4] = pk2(eaB.x, eaB.x); ea2[5] = pk2(eaB.y, eaB.y);
}

// ---------------- NNConv partial kernel: SPLIT blocks per node ----------------
template <int IN, int OUT, int OPAD, int BLOCK>
__global__ void __launch_bounds__(BLOCK) nnconv_part_kernel(
    const float* __restrict__ h_in,
    const float* __restrict__ W, const float* __restrict__ b) {
    constexpr int NP = OPAD / 2;
    constexpr int S = BLOCK * SPLIT;
    __shared__ __align__(16) float sW[IN * NP * 16];
    __shared__ float red[BLOCK / 32][OPAD];
    const int tid = threadIdx.x;

    for (int idx = tid; idx < IN * NP; idx += BLOCK) {
        int i = idx / NP, p = idx % NP;
        float* t = sW + idx * 16;
        int o0 = 2 * p, o1 = 2 * p + 1;
#pragma unroll
        for (int v = 0; v < 6; v++) {
            t[2 * v]     = (o0 < OUT) ? W[v * (IN * OUT) + i * OUT + o0] : 0.0f;
            t[2 * v + 1] = (o1 < OUT) ? W[v * (IN * OUT) + i * OUT + o1] : 0.0f;
        }
        t[12] = (o0 < OUT) ? b[i * OUT + o0] : 0.0f;
        t[13] = (o1 < OUT) ? b[i * OUT + o1] : 0.0f;
        t[14] = 0.0f; t[15] = 0.0f;
    }
    __syncthreads();

    const int n = blockIdx.x / SPLIT;
    const int part = blockIdx.x % SPLIT;
    const int e0 = g_start[n], e1 = g_start[n + 1];

    float acc[OPAD];
#pragma unroll
    for (int o = 0; o < OPAD; o++) acc[o] = 0.0f;

    int e = e0 + part * BLOCK + tid;
    for (; e + S < e1; e += 2 * S) {
        int eA = e, eB = e + S;
        int sA = g_src_sorted[eA], sB = g_src_sorted[eB];
        unsigned long long eaA[6], eaB[6];
        load_ea(eA, eaA);
        load_ea(eB, eaB);
        if constexpr (IN == 1) {
            float xA = h_in[sA], xB = h_in[sB];
            edge_tile2<NP>((const ulonglong2*)sW, eaA, eaB, xA, xB, acc);
        } else {
#pragma unroll 1
            for (int i4 = 0; i4 < IN / 4; i4++) {
                float4 xvA = *(const float4*)(h_in + (size_t)sA * IN + 4 * i4);
                float4 xvB = *(const float4*)(h_in + (size_t)sB * IN + 4 * i4);
                float xsA[4] = {xvA.x, xvA.y, xvA.z, xvA.w};
                float xsB[4] = {xvB.x, xvB.y, xvB.z, xvB.w};
#pragma unroll
                for (int su = 0; su < 4; su++) {
                    const ulonglong2* tp =
                        (const ulonglong2*)(sW + (size_t)(i4 * 4 + su) * NP * 16);
                    edge_tile2<NP>(tp, eaA, eaB, xsA[su], xsB[su], acc);
                }
            }
        }
    }
    for (; e < e1; e += S) {
        int s = g_src_sorted[e];
        unsigned long long ea2[6];
        load_ea(e, ea2);
        if constexpr (IN == 1) {
            float xi = h_in[s];
            edge_tile<NP>((const ulonglong2*)sW, ea2, xi, acc);
        } else {
#pragma unroll 1
            for (int i4 = 0; i4 < IN / 4; i4++) {
                float4 xv = *(const float4*)(h_in + (size_t)s * IN + 4 * i4);
                float xs[4] = {xv.x, xv.y, xv.z, xv.w};
#pragma unroll
                for (int su = 0; su < 4; su++) {
                    const ulonglong2* tp =
                        (const ulonglong2*)(sW + (size_t)(i4 * 4 + su) * NP * 16);
                    edge_tile<NP>(tp, ea2, xs[su], acc);
                }
            }
        }
    }

    // warp reduce
#pragma unroll
    for (int o = 0; o < OPAD; o++) {
        float v = acc[o];
        v += __shfl_down_sync(0xffffffffu, v, 16);
        v += __shfl_down_sync(0xffffffffu, v, 8);
        v += __shfl_down_sync(0xffffffffu, v, 4);
        v += __shfl_down_sync(0xffffffffu, v, 2);
        v += __shfl_down_sync(0xffffffffu, v, 1);
        acc[o] = v;
    }
    if ((tid & 31) == 0) {
#pragma unroll
        for (int o = 0; o < OPAD; o++) red[tid >> 5][o] = acc[o];
    }
    __syncthreads();

    if (tid < OUT) {
        float s = 0.0f;
#pragma unroll
        for (int w = 0; w < BLOCK / 32; w++) s += red[w][tid];
        g_part[(size_t)blockIdx.x * PSTRIDE + tid] = s;
    }
}

// ---------------- combine: mean + root + bias + relu --------------------------
template <int IN, int OUT>
__global__ void __launch_bounds__(256) combine_kernel(
    const float* __restrict__ h_in,
    const float* __restrict__ root, const float* __restrict__ bias,
    float* __restrict__ h_out) {
    int idx = blockIdx.x * 256 + threadIdx.x;
    if (idx >= NN * OUT) return;
    int n = idx / OUT, o = idx - n * OUT;
    float s = 0.0f;
#pragma unroll
    for (int k = 0; k < SPLIT; k++)
        s += g_part[(size_t)(n * SPLIT + k) * PSTRIDE + o];
    s *= g_invcnt[n];
    float r = 0.0f;
#pragma unroll
    for (int i = 0; i < IN; i++) r += h_in[(size_t)n * IN + i] * root[i * OUT + o];
    h_out[idx] = fmaxf(s + r + bias[o], 0.0f);
}

// ---------------- CBT ----------------
__global__ void cbt_kernel(const float* __restrict__ h3, float* __restrict__ out) {
    __shared__ float sh[NN * 5];
    int tid = threadIdx.x;
    for (int i = tid; i < NN * 5; i += blockDim.x) sh[i] = h3[i];
    __syncthreads();
    int a = blockIdx.x;
    float ha[5];
#pragma unroll
    for (int f = 0; f < 5; f++) ha[f] = sh[a * 5 + f];
    float s = 0.0f;
#pragma unroll
    for (int f = 0; f < 5; f++) s += fabsf(sh[tid * 5 + f] - ha[f]);
    out[(size_t)a * NN + tid] = s;
}

// ---------------- launch ----------------
extern "C" void kernel_launch(void* const* d_in, const int* in_sizes, int n_in,
                              void* d_out, int out_size) {
    const float* x    = (const float*)d_in[0];
    const float* ea   = (const float*)d_in[1];
    const int*   eidx = (const int*)d_in[2];
    const float *W1 = (const float*)d_in[3],  *b1 = (const float*)d_in[4];
    const float *root1 = (const float*)d_in[5], *bias1 = (const float*)d_in[6];
    const float *W2 = (const float*)d_in[7],  *b2 = (const float*)d_in[8];
    const float *root2 = (const float*)d_in[9], *bias2 = (const float*)d_in[10];
    const float *W3 = (const float*)d_in[11], *b3 = (const float*)d_in[12];
    const float *root3 = (const float*)d_in[13], *bias3 = (const float*)d_in[14];
    float* out = (float*)d_out;

    detect_kernel<<<1, NN>>>(eidx);
    histA_kernel<<<NB, 256>>>(eidx);
    totals_kernel<<<NN / 64, 64>>>();
    scanB_kernel<<<1, NN>>>();
    offsets_kernel<<<NN / 64, 64>>>();
    scatterC_kernel<<<NB, 256>>>(eidx, ea);

    float* h1; cudaGetSymbolAddress((void**)&h1, g_h1);
    float* h2; cudaGetSymbolAddress((void**)&h2, g_h2);
    float* h3; cudaGetSymbolAddress((void**)&h3, g_h3);

    nnconv_part_kernel<1, 36, 36, 128><<<NN * SPLIT, 128>>>(x, W1, b1);
    combine_kernel<1, 36><<<(NN * 36 + 255) / 256, 256>>>(x, root1, bias1, h1);
    nnconv_part_kernel<36, 24, 24, 128><<<NN * SPLIT, 128>>>(h1, W2, b2);
    combine_kernel<36, 24><<<(NN * 24 + 255) / 256, 256>>>(h1, root2, bias2, h2);
    nnconv_part_kernel<24, 5, 6, 128><<<NN * SPLIT, 128>>>(h2, W3, b3);
    combine_kernel<24, 5><<<(NN * 5 + 255) / 256, 256>>>(h2, root3, bias3, h3);
    cbt_kernel<<<NN, NN>>>(h3, out);
}

// round 12
// speedup vs baseline: 1.2002x; 1.1519x over previous
#include <cuda_runtime.h>
#include <cuda_bf16.h>

#define NN 512
#define EE (NN * NN)
#define NB 256           // histogram blocks
#define CHUNK (EE / NB)  // 1024 edges per block

// ---------------- scratch ----------------
__device__ int   g_start[NN + 1];
__device__ float g_invcnt[NN];
__device__ int   g_bh[NB * NN];      // [block][bin] counts (coalesced layout)
__device__ int   g_bhoff[NB * NN];   // [block][bin] start offsets
__device__ int   g_src_sorted[EE];
__device__ __align__(16) float g_ea_sorted[EE * 8];
__device__ __align__(16) float g_h1[NN * 36];
__device__ __align__(16) float g_h2[NN * 24];
__device__ __align__(16) float g_h3[NN * 5];

// ---------------- packed f32x2 helpers ----------------
__device__ __forceinline__ unsigned long long pk2(float lo, float hi) {
    unsigned long long r;
    asm("mov.b64 %0,{%1,%2};" : "=l"(r) : "f"(lo), "f"(hi));
    return r;
}
__device__ __forceinline__ void upk2(unsigned long long v, float& lo, float& hi) {
    asm("mov.b64 {%0,%1},%2;" : "=f"(lo), "=f"(hi) : "l"(v));
}
__device__ __forceinline__ unsigned long long ffma2(unsigned long long a,
                                                    unsigned long long b,
                                                    unsigned long long c) {
    unsigned long long d;
    asm("fma.rn.f32x2 %0,%1,%2,%3;" : "=l"(d) : "l"(a), "l"(b), "l"(c));
    return d;
}

__device__ __forceinline__ int load_src(const int* raw, int e, int is64) {
    return (is64 ? raw[2 * e] : raw[e]) & (NN - 1);
}
__device__ __forceinline__ int load_dst(const int* raw, int e, int is64) {
    return (is64 ? raw[2 * EE + 2 * e] : raw[EE + e]) & (NN - 1);
}

// per-block dtype detect: sample 256 odd 32-bit words of this block's chunk.
// int64 input (values < 512) -> odd words all zero; int32 random -> nonzero whp.
__device__ __forceinline__ int block_detect_is64(const int* raw, int base, int tid) {
    int found = 0;
    if (tid < 256) {
        int e = base + 4 * tid;          // stays inside chunk (CHUNK=1024)
        if (raw[2 * e + 1] != 0) found = 1;
    }
    return (__syncthreads_or(found) == 0) ? 1 : 0;
}

// ---------------- 1: per-block histogram (inline detect) ----------------------
__global__ void __launch_bounds__(256) histA_kernel(const int* __restrict__ raw) {
    __shared__ int h[NN];
    int tid = threadIdx.x;
    int base = blockIdx.x * CHUNK;
    int is64 = block_detect_is64(raw, base, tid);
    for (int i = tid; i < NN; i += 256) h[i] = 0;
    __syncthreads();
#pragma unroll
    for (int k = 0; k < CHUNK / 256; k++) {
        int e = base + k * 256 + tid;
        atomicAdd(&h[load_dst(raw, e, is64)], 1);
    }
    __syncthreads();
    for (int i = tid; i < NN; i += 256)
        g_bh[blockIdx.x * NN + i] = h[i];
}

// ---------------- 2: merged totals + scan + offsets (single block, coalesced) -
__global__ void __launch_bounds__(NN) mscan_kernel() {
    __shared__ int sc[NN];
    int t = threadIdx.x;
    int total = 0;
#pragma unroll 8
    for (int blk = 0; blk < NB; blk++) total += g_bh[blk * NN + t];
    sc[t] = total;
    __syncthreads();
    for (int off = 1; off < NN; off <<= 1) {
        int v = (t >= off) ? sc[t - off] : 0;
        __syncthreads();
        sc[t] += v;
        __syncthreads();
    }
    int base = sc[t] - total;
    g_start[t] = base;
    if (t == NN - 1) g_start[NN] = sc[t];
    g_invcnt[t] = 1.0f / (float)(total > 1 ? total : 1);
    int run = base;
#pragma unroll 8
    for (int blk = 0; blk < NB; blk++) {
        g_bhoff[blk * NN + t] = run;
        run += g_bh[blk * NN + t];
    }
}

// ---------------- 3: rank via smem atomics, direct sorted writes --------------
__global__ void __launch_bounds__(256) scatterC_kernel(const int* __restrict__ raw,
                                                       const float* __restrict__ ea) {
    __shared__ int loc[NN];
    int tid = threadIdx.x;
    int base = blockIdx.x * CHUNK;
    int is64 = block_detect_is64(raw, base, tid);
    for (int i = tid; i < NN; i += 256)
        loc[i] = g_bhoff[blockIdx.x * NN + i];
    __syncthreads();
#pragma unroll
    for (int k = 0; k < CHUNK / 256; k++) {
        int e = base + k * 256 + tid;
        int d = load_dst(raw, e, is64);
        int s = load_src(raw, e, is64);
        int pos = atomicAdd(&loc[d], 1);
        const float* q = ea + (size_t)e * 6;
        float v0 = q[0], v1 = q[1], v2 = q[2], v3 = q[3], v4 = q[4], v5 = q[5];
        g_src_sorted[pos] = s;
        float4* w = (float4*)(g_ea_sorted + (size_t)pos * 8);
        w[0] = make_float4(v0, v1, v2, v3);
        w[1] = make_float4(v4, v5, 0.0f, 0.0f);
    }
}

// ---------------- per-tile compute helpers (2-edge, packed f32x2 acc) ---------
template <int NP>
__device__ __forceinline__ void edge_tile(const ulonglong2* tp,
                                          const unsigned long long* ea2,
                                          unsigned long long xi2,
                                          unsigned long long* acc2) {
#pragma unroll
    for (int p = 0; p < NP; p++) {
        ulonglong2 w01 = tp[4 * p + 0];
        ulonglong2 w23 = tp[4 * p + 1];
        ulonglong2 w45 = tp[4 * p + 2];
        ulonglong2 bb  = tp[4 * p + 3];
        unsigned long long t = bb.x;
        t = ffma2(ea2[0], w01.x, t);
        t = ffma2(ea2[1], w01.y, t);
        t = ffma2(ea2[2], w23.x, t);
        t = ffma2(ea2[3], w23.y, t);
        t = ffma2(ea2[4], w45.x, t);
        t = ffma2(ea2[5], w45.y, t);
        float t0, t1; upk2(t, t0, t1);
        t0 = fmaxf(t0, 0.0f); t1 = fmaxf(t1, 0.0f);
        acc2[p] = ffma2(xi2, pk2(t0, t1), acc2[p]);
    }
}

template <int NP>
__device__ __forceinline__ void edge_tile2(const ulonglong2* tp,
                                           const unsigned long long* eaA,
                                           const unsigned long long* eaB,
                                           unsigned long long xiA2,
                                           unsigned long long xiB2,
                                           unsigned long long* acc2) {
#pragma unroll
    for (int p = 0; p < NP; p++) {
        ulonglong2 w01 = tp[4 * p + 0];
        ulonglong2 w23 = tp[4 * p + 1];
        ulonglong2 w45 = tp[4 * p + 2];
        ulonglong2 bb  = tp[4 * p + 3];
        unsigned long long tA = bb.x, tB = bb.x;
        tA = ffma2(eaA[0], w01.x, tA);  tB = ffma2(eaB[0], w01.x, tB);
        tA = ffma2(eaA[1], w01.y, tA);  tB = ffma2(eaB[1], w01.y, tB);
        tA = ffma2(eaA[2], w23.x, tA);  tB = ffma2(eaB[2], w23.x, tB);
        tA = ffma2(eaA[3], w23.y, tA);  tB = ffma2(eaB[3], w23.y, tB);
        tA = ffma2(eaA[4], w45.x, tA);  tB = ffma2(eaB[4], w45.x, tB);
        tA = ffma2(eaA[5], w45.y, tA);  tB = ffma2(eaB[5], w45.y, tB);
        float a0, a1, b0, b1;
        upk2(tA, a0, a1); upk2(tB, b0, b1);
        a0 = fmaxf(a0, 0.0f); a1 = fmaxf(a1, 0.0f);
        b0 = fmaxf(b0, 0.0f); b1 = fmaxf(b1, 0.0f);
        unsigned long long s = ffma2(xiA2, pk2(a0, a1), acc2[p]);
        acc2[p] = ffma2(xiB2, pk2(b0, b1), s);
    }
}

__device__ __forceinline__ void load_ea(int e, unsigned long long* ea2) {
    float4 eaA = *(const float4*)(g_ea_sorted + (size_t)e * 8);
    float4 eaB = *(const float4*)(g_ea_sorted + (size_t)e * 8 + 4);
    ea2[0] = pk2(eaA.x, eaA.x); ea2[1] = pk2(eaA.y, eaA.y);
    ea2[2] = pk2(eaA.z, eaA.z); ea2[3] = pk2(eaA.w, eaA.w);
    ea2[4] = pk2(eaB.x, eaB.x); ea2[5] = pk2(eaB.y, eaB.y);
}

// ---------------- fused NNConv layer (gather form) ----------------
template <int IN, int OUT, int OPAD, int BLOCK>
__global__ void __launch_bounds__(BLOCK) nnconv_kernel(
    const float* __restrict__ h_in,
    const float* __restrict__ W, const float* __restrict__ b,
    const float* __restrict__ root, const float* __restrict__ bias,
    float* __restrict__ h_out) {
    constexpr int NP = OPAD / 2;
    __shared__ __align__(16) float sW[IN * NP * 16];
    __shared__ float red[BLOCK / 32][OPAD];
    const int tid = threadIdx.x;

    for (int idx = tid; idx < IN * NP; idx += BLOCK) {
        int i = idx / NP, p = idx % NP;
        float* t = sW + idx * 16;
        int o0 = 2 * p, o1 = 2 * p + 1;
#pragma unroll
        for (int v = 0; v < 6; v++) {
            t[2 * v]     = (o0 < OUT) ? W[v * (IN * OUT) + i * OUT + o0] : 0.0f;
            t[2 * v + 1] = (o1 < OUT) ? W[v * (IN * OUT) + i * OUT + o1] : 0.0f;
        }
        t[12] = (o0 < OUT) ? b[i * OUT + o0] : 0.0f;
        t[13] = (o1 < OUT) ? b[i * OUT + o1] : 0.0f;
        t[14] = 0.0f; t[15] = 0.0f;
    }
    __syncthreads();

    const int n = blockIdx.x;
    const int e0 = g_start[n], e1 = g_start[n + 1];

    unsigned long long acc2[NP];
#pragma unroll
    for (int p = 0; p < NP; p++) acc2[p] = 0ull;

    int e = e0 + tid;
    for (; e + BLOCK < e1; e += 2 * BLOCK) {
        int eA = e, eB = e + BLOCK;
        int sA = g_src_sorted[eA], sB = g_src_sorted[eB];
        unsigned long long eaA[6], eaB[6];
        load_ea(eA, eaA);
        load_ea(eB, eaB);
        if constexpr (IN == 1) {
            float xA = h_in[sA], xB = h_in[sB];
            edge_tile2<NP>((const ulonglong2*)sW, eaA, eaB,
                           pk2(xA, xA), pk2(xB, xB), acc2);
        } else {
#pragma unroll 1
            for (int i4 = 0; i4 < IN / 4; i4++) {
                float4 xvA = *(const float4*)(h_in + (size_t)sA * IN + 4 * i4);
                float4 xvB = *(const float4*)(h_in + (size_t)sB * IN + 4 * i4);
                float xsA[4] = {xvA.x, xvA.y, xvA.z, xvA.w};
                float xsB[4] = {xvB.x, xvB.y, xvB.z, xvB.w};
#pragma unroll
                for (int su = 0; su < 4; su++) {
                    const ulonglong2* tp =
                        (const ulonglong2*)(sW + (size_t)(i4 * 4 + su) * NP * 16);
                    edge_tile2<NP>(tp, eaA, eaB,
                                   pk2(xsA[su], xsA[su]), pk2(xsB[su], xsB[su]), acc2);
                }
            }
        }
    }
    if (e < e1) {
        int s = g_src_sorted[e];
        unsigned long long ea2[6];
        load_ea(e, ea2);
        if constexpr (IN == 1) {
            float xi = h_in[s];
            edge_tile<NP>((const ulonglong2*)sW, ea2, pk2(xi, xi), acc2);
        } else {
#pragma unroll 1
            for (int i4 = 0; i4 < IN / 4; i4++) {
                float4 xv = *(const float4*)(h_in + (size_t)s * IN + 4 * i4);
                float xs[4] = {xv.x, xv.y, xv.z, xv.w};
#pragma unroll
                for (int su = 0; su < 4; su++) {
                    const ulonglong2* tp =
                        (const ulonglong2*)(sW + (size_t)(i4 * 4 + su) * NP * 16);
                    edge_tile<NP>(tp, ea2, pk2(xs[su], xs[su]), acc2);
                }
            }
        }
    }

    // unpack + warp reduce
    float acc[OPAD];
#pragma unroll
    for (int p = 0; p < NP; p++) upk2(acc2[p], acc[2 * p], acc[2 * p + 1]);
#pragma unroll
    for (int o = 0; o < OPAD; o++) {
        float v = acc[o];
        v += __shfl_down_sync(0xffffffffu, v, 16);
        v += __shfl_down_sync(0xffffffffu, v, 8);
        v += __shfl_down_sync(0xffffffffu, v, 4);
        v += __shfl_down_sync(0xffffffffu, v, 2);
        v += __shfl_down_sync(0xffffffffu, v, 1);
        acc[o] = v;
    }
    if ((tid & 31) == 0) {
#pragma unroll
        for (int o = 0; o < OPAD; o++) red[tid >> 5][o] = acc[o];
    }
    __syncthreads();

    if (tid < OUT) {
        float s = 0.0f;
#pragma unroll
        for (int w = 0; w < BLOCK / 32; w++) s += red[w][tid];
        s *= g_invcnt[n];
        float r = 0.0f;
#pragma unroll
        for (int i = 0; i < IN; i++) r += h_in[(size_t)n * IN + i] * root[i * OUT + tid];
        float v = s + r + bias[tid];
        h_out[(size_t)n * OUT + tid] = fmaxf(v, 0.0f);
    }
}

// ---------------- CBT ----------------
__global__ void cbt_kernel(const float* __restrict__ h3, float* __restrict__ out) {
    __shared__ float sh[NN * 5];
    int tid = threadIdx.x;
    for (int i = tid; i < NN * 5; i += blockDim.x) sh[i] = h3[i];
    __syncthreads();
    int a = blockIdx.x;
    float ha[5];
#pragma unroll
    for (int f = 0; f < 5; f++) ha[f] = sh[a * 5 + f];
    float s = 0.0f;
#pragma unroll
    for (int f = 0; f < 5; f++) s += fabsf(sh[tid * 5 + f] - ha[f]);
    out[(size_t)a * NN + tid] = s;
}

// ---------------- launch ----------------
extern "C" void kernel_launch(void* const* d_in, const int* in_sizes, int n_in,
                              void* d_out, int out_size) {
    const float* x    = (const float*)d_in[0];
    const float* ea   = (const float*)d_in[1];
    const int*   eidx = (const int*)d_in[2];
    const float *W1 = (const float*)d_in[3],  *b1 = (const float*)d_in[4];
    const float *root1 = (const float*)d_in[5], *bias1 = (const float*)d_in[6];
    const float *W2 = (const float*)d_in[7],  *b2 = (const float*)d_in[8];
    const float *root2 = (const float*)d_in[9], *bias2 = (const float*)d_in[10];
    const float *W3 = (const float*)d_in[11], *b3 = (const float*)d_in[12];
    const float *root3 = (const float*)d_in[13], *bias3 = (const float*)d_in[14];
    float* out = (float*)d_out;

    float* h1; cudaGetSymbolAddress((void**)&h1, g_h1);
    float* h2; cudaGetSymbolAddress((void**)&h2, g_h2);
    float* h3; cudaGetSymbolAddress((void**)&h3, g_h3);

    histA_kernel<<<NB, 256>>>(eidx);                                   // 1
    mscan_kernel<<<1, NN>>>();                                         // 2
    scatterC_kernel<<<NB, 256>>>(eidx, ea);                            // 3
    nnconv_kernel<1, 36, 36, 128><<<NN, 128>>>(x,  W1, b1, root1, bias1, h1);  // 4 <- ncu
    nnconv_kernel<36, 24, 24, 128><<<NN, 128>>>(h1, W2, b2, root2, bias2, h2); // 5
    nnconv_kernel<24, 5, 6, 128><<<NN, 128>>>(h2, W3, b3, root3, bias3, h3);   // 6
    cbt_kernel<<<NN, NN>>>(h3, out);                                   // 7
}